// round 11
// baseline (speedup 1.0000x reference)
#include <cuda_runtime.h>
#include <math.h>

#define J   23
#define TPB 256
#define VPB 256
#define PI_F 3.14159265358979323846f

__constant__ int cPAR[J] = {-1,0,1,1,3,4,5,4,7,4,9,1,11,12,13,12,15,12,17,0,19,0,21};

// packed A (69 float4 = 276 floats) + constants (c, ox, oy, oz) at [276..279]
__constant__ __align__(16) float c_pack[280];

typedef unsigned long long u64;

__device__ __forceinline__ void fma2(u64& d, u64 a, u64 b) {
    asm("fma.rn.f32x2 %0, %1, %2, %0;" : "+l"(d) : "l"(a), "l"(b));
}
__device__ __forceinline__ u64 pack2(float v) {
    u64 r;
    asm("mov.b64 %0, {%1, %1};" : "=l"(r) : "f"(v));
    return r;
}
__device__ __forceinline__ void unpack2(u64 v, float& lo, float& hi) {
    asm("mov.b64 {%0, %1}, %2;" : "=f"(lo), "=f"(hi) : "l"(v));
}
__device__ __forceinline__ float tanha(float x) {
    float y;
    asm("tanh.approx.f32 %0, %1;" : "=f"(y) : "f"(x));
    return y;
}

// ---------------- Prep: one warp; writes A + consts into the constant bank, triggers PDL ----------------
__global__ void __launch_bounds__(32) prep_kernel(
    float* __restrict__ cpack,
    const float* __restrict__ jr,
    const float* __restrict__ p0, const float* __restrict__ p1,
    const float* __restrict__ p2, const float* __restrict__ p3,
    const float* __restrict__ p4, const float* __restrict__ p5,
    const float* __restrict__ p12, const float* __restrict__ p13,
    const float* __restrict__ disp, const float* __restrict__ scale,
    const float* __restrict__ loc,
    float* __restrict__ out, int B, int V)
{
    __shared__ float s_Tl[J * 12];
    __shared__ float s_G[J * 12];
    __shared__ float s_pose[J * 3];

    const int tid = threadIdx.x;

    float cst = 0.f, ox = 0.f, oy = 0.f, oz = 0.f;
    if (tid == 31) {
        cst = 0.0035f * scale[0];
        ox = loc[0] + 0.1f * tanhf(disp[0]);
        oy = loc[1] + 0.1f * tanhf(disp[1]);
        oz = loc[2] + 0.1f * tanhf(disp[2]);
        cpack[276] = cst; cpack[277] = ox; cpack[278] = oy; cpack[279] = oz;
    }

    if (tid < J) {
        float fac = 0.f, sy = 1.f, sz = 1.f;
        const float* pp = p0;
        bool has = true;
        switch (tid) {
            case 0:  fac = PI_F / 2.f; pp = p0;  break;
            case 1:  fac = PI_F / 4.f; pp = p1;  break;
            case 2:  fac = PI_F / 9.f; pp = p2;  break;
            case 3:  fac = PI_F / 3.f; pp = p3;  break;
            case 4:  fac = PI_F / 3.f; pp = p4;  break;
            case 5:  fac = PI_F / 3.f; pp = p5;  break;
            case 11: fac = PI_F / 3.f; pp = p3;  sy = -1.f; sz = -1.f; break;
            case 12: fac = PI_F / 3.f; pp = p12; break;
            case 13: fac = PI_F / 3.f; pp = p13; break;
            default: has = false;
        }
        float px = 0.f, py = 0.f, pz = 0.f;
        if (has) {
            px = fac * tanhf(pp[0]);
            py = sy * fac * tanhf(pp[1]);
            pz = sz * fac * tanhf(pp[2]);
        }
        s_pose[3 * tid + 0] = px;
        s_pose[3 * tid + 1] = py;
        s_pose[3 * tid + 2] = pz;

        float ang = sqrtf(px * px + py * py + pz * pz + 1e-12f);
        float inv = 1.f / ang;
        float x = px * inv, y = py * inv, z = pz * inv;
        float s = __sinf(ang), c = __cosf(ang), t = 1.f - c;
        float* T = &s_Tl[tid * 12];
        T[0] = 1.f + t * (-(z * z) - (y * y));
        T[1] = -s * z + t * (x * y);
        T[2] =  s * y + t * (x * z);
        T[4] =  s * z + t * (x * y);
        T[5] = 1.f + t * (-(z * z) - (x * x));
        T[6] = -s * x + t * (y * z);
        T[8] = -s * y + t * (x * z);
        T[9] =  s * x + t * (y * z);
        T[10] = 1.f + t * (-(y * y) - (x * x));

        int par = cPAR[tid];
        float jx = jr[3 * tid], jy = jr[3 * tid + 1], jz = jr[3 * tid + 2];
        if (par >= 0) { jx -= jr[3 * par]; jy -= jr[3 * par + 1]; jz -= jr[3 * par + 2]; }
        T[3] = jx; T[7] = jy; T[11] = jz;
    }
    __syncwarp();

    if (tid < 12) s_G[tid] = s_Tl[tid];
    __syncwarp();
    #pragma unroll
    for (int j = 1; j < J; j++) {
        const int p = cPAR[j];
        if (tid < 12) {
            const int r = tid >> 2, c = tid & 3;
            const float* gp = &s_G[p * 12 + r * 4];
            const float* tl = &s_Tl[j * 12];
            float v = gp[0] * tl[0 * 4 + c]
                    + gp[1] * tl[1 * 4 + c]
                    + gp[2] * tl[2 * 4 + c];
            if (c == 3) v += gp[3];
            s_G[j * 12 + tid] = v;
        }
        __syncwarp();
    }

    if (tid < J) {
        const float* g = &s_G[tid * 12];
        float jx = jr[3 * tid], jy = jr[3 * tid + 1], jz = jr[3 * tid + 2];
        float tcx = g[0] * jx + g[1] * jy + g[2] * jz;
        float tcy = g[4] * jx + g[5] * jy + g[6] * jz;
        float tcz = g[8] * jx + g[9] * jy + g[10] * jz;
        float* a = &cpack[tid * 12];
        a[0] = g[0]; a[1] = g[1]; a[2]  = g[2];  a[3]  = g[3]  - tcx;
        a[4] = g[4]; a[5] = g[5]; a[6]  = g[6];  a[7]  = g[7]  - tcy;
        a[8] = g[8]; a[9] = g[9]; a[10] = g[10]; a[11] = g[11] - tcz;
    }
    __syncwarp();
    __threadfence();
    cudaTriggerProgrammaticLaunchCompletion();

    // small outputs (independent of lbs)
    const long V3 = 3L * (long)V;
    const long base = (long)B * V3;
    if (tid < J) {
        out[base + 3 * tid + 0] = s_pose[3 * tid + 0];
        out[base + 3 * tid + 1] = s_pose[3 * tid + 1];
        out[base + 3 * tid + 2] = s_pose[3 * tid + 2];
    }
    if (tid == 31) {
        for (int j = 0; j < J; j++) {
            out[base + 69 + 3 * j + 0] = fmaf(cst, s_G[j * 12 + 3],  ox);
            out[base + 69 + 3 * j + 1] = fmaf(cst, s_G[j * 12 + 7],  oy);
            out[base + 69 + 3 * j + 2] = fmaf(cst, s_G[j * 12 + 11], oz);
        }
        out[base + 138] = scale[0];
        out[base + 139] = disp[0];
        out[base + 140] = disp[1];
        out[base + 141] = disp[2];
    }
}

// ---------------- LBS: PDL preamble (loads + tanh folded), constant-bank A, f32x2 ----------------
__global__ void __launch_bounds__(TPB, 7) lbs_kernel(
    const float* __restrict__ vt,
    const float* __restrict__ sk,
    const float* __restrict__ la,
    float* __restrict__ out, int V, int B)
{
    __shared__ float s_sk[VPB * 23];
    __shared__ float s_vh[VPB * 3];    // vh during compute, results after

    const int tid = threadIdx.x;
    const long v0 = (long)blockIdx.x * VPB;
    const int nv  = (V - (int)v0 < VPB) ? (V - (int)v0) : VPB;
    const long V3 = 3L * (long)V;
    const bool full = (nv == VPB);
    const long offLa = (long)B * V3 + 142;

    // ---- PDL preamble: tile loads, la passthrough, vh computation ----
    {
        const float4* g4 = (const float4*)(sk + v0 * 23);
        float4* d4 = (float4*)s_sk;
        const float4* gv = (const float4*)(vt + v0 * 3);
        const float4* gl = (const float4*)(la + v0 * 3);
        float4* dv = (float4*)s_vh;
        float2* gl2 = (float2*)(out + offLa + v0 * 3);
        if (full) {
            #pragma unroll
            for (int k = 0; k < 5; k++) {
                const int i = tid + k * TPB;
                d4[i] = __ldcs(g4 + i);
            }
            {
                const int i = tid + 5 * TPB;
                if (i < 1472) d4[i] = __ldcs(g4 + i);
            }
            if (tid < 192) {
                float4 vq = __ldcs(gv + tid);
                float4 lq = __ldcs(gl + tid);
                __stcs(gl2 + 2 * tid + 0, make_float2(lq.x, lq.y));
                __stcs(gl2 + 2 * tid + 1, make_float2(lq.z, lq.w));
                vq.x = fmaf(0.1f, tanha(lq.x), vq.x);
                vq.y = fmaf(0.1f, tanha(lq.y), vq.y);
                vq.z = fmaf(0.1f, tanha(lq.z), vq.z);
                vq.w = fmaf(0.1f, tanha(lq.w), vq.w);
                dv[tid] = vq;
            }
        } else {
            const int nS = (nv * 23) >> 2;
            for (int i = tid; i < nS; i += TPB) d4[i] = __ldcs(g4 + i);
            const int n3 = (nv * 3) >> 2;
            for (int i = tid; i < n3; i += TPB) {
                float4 vq = __ldcs(gv + i);
                float4 lq = __ldcs(gl + i);
                __stcs(gl2 + 2 * i + 0, make_float2(lq.x, lq.y));
                __stcs(gl2 + 2 * i + 1, make_float2(lq.z, lq.w));
                vq.x = fmaf(0.1f, tanha(lq.x), vq.x);
                vq.y = fmaf(0.1f, tanha(lq.y), vq.y);
                vq.z = fmaf(0.1f, tanha(lq.z), vq.z);
                vq.w = fmaf(0.1f, tanha(lq.w), vq.w);
                dv[i] = vq;
            }
        }
    }

    cudaGridDependencySynchronize();
    __syncthreads();

    if (tid < nv) {
        float vx = s_vh[3 * tid + 0];
        float vy = s_vh[3 * tid + 1];
        float vz = s_vh[3 * tid + 2];

        u64 acc0 = 0, acc1 = 0, acc2 = 0, acc3 = 0, acc4 = 0, acc5 = 0;
        const u64* cA2 = (const u64*)c_pack;
        const float* skv = &s_sk[tid * 23];
        #pragma unroll
        for (int j = 0; j < J; j++) {
            const u64 w2 = pack2(skv[j]);
            fma2(acc0, w2, cA2[6 * j + 0]);
            fma2(acc1, w2, cA2[6 * j + 1]);
            fma2(acc2, w2, cA2[6 * j + 2]);
            fma2(acc3, w2, cA2[6 * j + 3]);
            fma2(acc4, w2, cA2[6 * j + 4]);
            fma2(acc5, w2, cA2[6 * j + 5]);
        }

        float t0x, t0y, t0z, t0w, t1x, t1y, t1z, t1w, t2x, t2y, t2z, t2w;
        unpack2(acc0, t0x, t0y); unpack2(acc1, t0z, t0w);
        unpack2(acc2, t1x, t1y); unpack2(acc3, t1z, t1w);
        unpack2(acc4, t2x, t2y); unpack2(acc5, t2z, t2w);

        float x = fmaf(t0x, vx, fmaf(t0y, vy, fmaf(t0z, vz, t0w)));
        float y = fmaf(t1x, vx, fmaf(t1y, vy, fmaf(t1z, vz, t1w)));
        float z = fmaf(t2x, vx, fmaf(t2y, vy, fmaf(t2z, vz, t2w)));

        float c = c_pack[276];
        // overwrite own slots only -> no barrier needed before writes
        s_vh[3 * tid + 0] = fmaf(c, x, c_pack[277]);
        s_vh[3 * tid + 1] = fmaf(c, y, c_pack[278]);
        s_vh[3 * tid + 2] = fmaf(c, z, c_pack[279]);
    }
    __syncthreads();

    // cooperative vectorized streaming stores (B broadcast copies)
    {
        const float4* r4 = (const float4*)s_vh;
        const long stride4 = V3 >> 2;
        if (full) {
            if (tid < 192) {
                const float4 val = r4[tid];
                float4* go = (float4*)(out + v0 * 3);
                for (int b = 0; b < B; b++) {
                    __stcs(go + tid, val);
                    go += stride4;
                }
            }
        } else {
            const int n3 = (nv * 3) >> 2;
            float4* go = (float4*)(out + v0 * 3);
            for (int b = 0; b < B; b++) {
                for (int i = tid; i < n3; i += TPB) __stcs(go + i, r4[i]);
                go += stride4;
            }
        }
    }
}

extern "C" void kernel_launch(void* const* d_in, const int* in_sizes, int n_in,
                              void* d_out, int out_size)
{
    const float* vt    = (const float*)d_in[0];
    const float* sk    = (const float*)d_in[1];
    const float* jr    = (const float*)d_in[2];
    const float* p0    = (const float*)d_in[3];
    const float* p1    = (const float*)d_in[4];
    const float* p2    = (const float*)d_in[5];
    const float* p3    = (const float*)d_in[6];
    const float* p4    = (const float*)d_in[7];
    const float* p5    = (const float*)d_in[8];
    const float* p12   = (const float*)d_in[9];
    const float* p13   = (const float*)d_in[10];
    const float* la    = (const float*)d_in[11];
    const float* disp  = (const float*)d_in[12];
    const float* scale = (const float*)d_in[13];
    const float* loc   = (const float*)d_in[14];
    float* out = (float*)d_out;

    int V = in_sizes[0] / 3;
    long fixed = 69L + 69L + 1L + 3L + 3L * (long)V;
    int B = (int)(((long)out_size - fixed) / (3L * (long)V));

    static float* cpack_dev = nullptr;
    if (!cpack_dev) {
        void* p = nullptr;
        cudaGetSymbolAddress(&p, c_pack);
        cpack_dev = (float*)p;
    }

    prep_kernel<<<1, 32>>>(cpack_dev, jr, p0, p1, p2, p3, p4, p5, p12, p13,
                           disp, scale, loc, out, B, V);

    int blocks = (V + VPB - 1) / VPB;

    cudaLaunchConfig_t cfg = {};
    cfg.gridDim  = dim3(blocks, 1, 1);
    cfg.blockDim = dim3(TPB, 1, 1);
    cfg.dynamicSmemBytes = 0;
    cfg.stream = 0;
    cudaLaunchAttribute attrs[1];
    attrs[0].id = cudaLaunchAttributeProgrammaticStreamSerialization;
    attrs[0].val.programmaticStreamSerializationAllowed = 1;
    cfg.attrs = attrs;
    cfg.numAttrs = 1;
    cudaLaunchKernelEx(&cfg, lbs_kernel, vt, sk, la, out, V, B);
}

// round 12
// speedup vs baseline: 1.0477x; 1.0477x over previous
#include <cuda_runtime.h>
#include <math.h>

#define J   23
#define TPB 256
#define VPB 256
#define PI_F 3.14159265358979323846f

__constant__ int cPAR[J] = {-1,0,1,1,3,4,5,4,7,4,9,1,11,12,13,12,15,12,17,0,19,0,21};

// packed A (69 float4 = 276 floats) + constants (c, ox, oy, oz) at [276..279]
__constant__ __align__(16) float c_pack[280];

typedef unsigned long long u64;

__device__ __forceinline__ void fma2(u64& d, u64 a, u64 b) {
    asm("fma.rn.f32x2 %0, %1, %2, %0;" : "+l"(d) : "l"(a), "l"(b));
}
__device__ __forceinline__ u64 pack2(float v) {
    u64 r;
    asm("mov.b64 %0, {%1, %1};" : "=l"(r) : "f"(v));
    return r;
}
__device__ __forceinline__ void unpack2(u64 v, float& lo, float& hi) {
    asm("mov.b64 {%0, %1}, %2;" : "=f"(lo), "=f"(hi) : "l"(v));
}
__device__ __forceinline__ float tanha(float x) {
    float y;
    asm("tanh.approx.f32 %0, %1;" : "=f"(y) : "f"(x));
    return y;
}

// ---------------- Prep: one warp; writes A + consts into the constant bank, triggers PDL ----------------
__global__ void __launch_bounds__(32) prep_kernel(
    float* __restrict__ cpack,
    const float* __restrict__ jr,
    const float* __restrict__ p0, const float* __restrict__ p1,
    const float* __restrict__ p2, const float* __restrict__ p3,
    const float* __restrict__ p4, const float* __restrict__ p5,
    const float* __restrict__ p12, const float* __restrict__ p13,
    const float* __restrict__ disp, const float* __restrict__ scale,
    const float* __restrict__ loc,
    float* __restrict__ out, int B, int V)
{
    __shared__ float s_Tl[J * 12];
    __shared__ float s_G[J * 12];
    __shared__ float s_pose[J * 3];

    const int tid = threadIdx.x;

    float cst = 0.f, ox = 0.f, oy = 0.f, oz = 0.f;
    if (tid == 31) {
        cst = 0.0035f * scale[0];
        ox = loc[0] + 0.1f * tanhf(disp[0]);
        oy = loc[1] + 0.1f * tanhf(disp[1]);
        oz = loc[2] + 0.1f * tanhf(disp[2]);
        cpack[276] = cst; cpack[277] = ox; cpack[278] = oy; cpack[279] = oz;
    }

    if (tid < J) {
        float fac = 0.f, sy = 1.f, sz = 1.f;
        const float* pp = p0;
        bool has = true;
        switch (tid) {
            case 0:  fac = PI_F / 2.f; pp = p0;  break;
            case 1:  fac = PI_F / 4.f; pp = p1;  break;
            case 2:  fac = PI_F / 9.f; pp = p2;  break;
            case 3:  fac = PI_F / 3.f; pp = p3;  break;
            case 4:  fac = PI_F / 3.f; pp = p4;  break;
            case 5:  fac = PI_F / 3.f; pp = p5;  break;
            case 11: fac = PI_F / 3.f; pp = p3;  sy = -1.f; sz = -1.f; break;
            case 12: fac = PI_F / 3.f; pp = p12; break;
            case 13: fac = PI_F / 3.f; pp = p13; break;
            default: has = false;
        }
        float px = 0.f, py = 0.f, pz = 0.f;
        if (has) {
            px = fac * tanhf(pp[0]);
            py = sy * fac * tanhf(pp[1]);
            pz = sz * fac * tanhf(pp[2]);
        }
        s_pose[3 * tid + 0] = px;
        s_pose[3 * tid + 1] = py;
        s_pose[3 * tid + 2] = pz;

        float ang = sqrtf(px * px + py * py + pz * pz + 1e-12f);
        float inv = 1.f / ang;
        float x = px * inv, y = py * inv, z = pz * inv;
        float s = __sinf(ang), c = __cosf(ang), t = 1.f - c;
        float* T = &s_Tl[tid * 12];
        T[0] = 1.f + t * (-(z * z) - (y * y));
        T[1] = -s * z + t * (x * y);
        T[2] =  s * y + t * (x * z);
        T[4] =  s * z + t * (x * y);
        T[5] = 1.f + t * (-(z * z) - (x * x));
        T[6] = -s * x + t * (y * z);
        T[8] = -s * y + t * (x * z);
        T[9] =  s * x + t * (y * z);
        T[10] = 1.f + t * (-(y * y) - (x * x));

        int par = cPAR[tid];
        float jx = jr[3 * tid], jy = jr[3 * tid + 1], jz = jr[3 * tid + 2];
        if (par >= 0) { jx -= jr[3 * par]; jy -= jr[3 * par + 1]; jz -= jr[3 * par + 2]; }
        T[3] = jx; T[7] = jy; T[11] = jz;
    }
    __syncwarp();

    if (tid < 12) s_G[tid] = s_Tl[tid];
    __syncwarp();
    #pragma unroll
    for (int j = 1; j < J; j++) {
        const int p = cPAR[j];
        if (tid < 12) {
            const int r = tid >> 2, c = tid & 3;
            const float* gp = &s_G[p * 12 + r * 4];
            const float* tl = &s_Tl[j * 12];
            float v = gp[0] * tl[0 * 4 + c]
                    + gp[1] * tl[1 * 4 + c]
                    + gp[2] * tl[2 * 4 + c];
            if (c == 3) v += gp[3];
            s_G[j * 12 + tid] = v;
        }
        __syncwarp();
    }

    if (tid < J) {
        const float* g = &s_G[tid * 12];
        float jx = jr[3 * tid], jy = jr[3 * tid + 1], jz = jr[3 * tid + 2];
        float tcx = g[0] * jx + g[1] * jy + g[2] * jz;
        float tcy = g[4] * jx + g[5] * jy + g[6] * jz;
        float tcz = g[8] * jx + g[9] * jy + g[10] * jz;
        float* a = &cpack[tid * 12];
        a[0] = g[0]; a[1] = g[1]; a[2]  = g[2];  a[3]  = g[3]  - tcx;
        a[4] = g[4]; a[5] = g[5]; a[6]  = g[6];  a[7]  = g[7]  - tcy;
        a[8] = g[8]; a[9] = g[9]; a[10] = g[10]; a[11] = g[11] - tcz;
    }
    __syncwarp();
    __threadfence();
    cudaTriggerProgrammaticLaunchCompletion();

    // small outputs (independent of lbs)
    const long V3 = 3L * (long)V;
    const long base = (long)B * V3;
    if (tid < J) {
        out[base + 3 * tid + 0] = s_pose[3 * tid + 0];
        out[base + 3 * tid + 1] = s_pose[3 * tid + 1];
        out[base + 3 * tid + 2] = s_pose[3 * tid + 2];
    }
    if (tid == 31) {
        for (int j = 0; j < J; j++) {
            out[base + 69 + 3 * j + 0] = fmaf(cst, s_G[j * 12 + 3],  ox);
            out[base + 69 + 3 * j + 1] = fmaf(cst, s_G[j * 12 + 7],  oy);
            out[base + 69 + 3 * j + 2] = fmaf(cst, s_G[j * 12 + 11], oz);
        }
        out[base + 138] = scale[0];
        out[base + 139] = disp[0];
        out[base + 140] = disp[1];
        out[base + 141] = disp[2];
    }
}

// ---------------- LBS: PDL preamble (loads + tanh folded), constant-bank A, f32x2 ----------------
__global__ void __launch_bounds__(TPB, 6) lbs_kernel(
    const float* __restrict__ vt,
    const float* __restrict__ sk,
    const float* __restrict__ la,
    float* __restrict__ out, int V, int B)
{
    __shared__ float s_sk[VPB * 23];
    __shared__ float s_vh[VPB * 3];    // vh during compute, results after

    const int tid = threadIdx.x;
    const long v0 = (long)blockIdx.x * VPB;
    const int nv  = (V - (int)v0 < VPB) ? (V - (int)v0) : VPB;
    const long V3 = 3L * (long)V;
    const bool full = (nv == VPB);
    const long offLa = (long)B * V3 + 142;

    // ---- PDL preamble: tile loads, la passthrough, vh computation ----
    {
        const float4* g4 = (const float4*)(sk + v0 * 23);
        float4* d4 = (float4*)s_sk;
        const float4* gv = (const float4*)(vt + v0 * 3);
        const float4* gl = (const float4*)(la + v0 * 3);
        float4* dv = (float4*)s_vh;
        float2* gl2 = (float2*)(out + offLa + v0 * 3);
        if (full) {
            #pragma unroll
            for (int k = 0; k < 5; k++) {
                const int i = tid + k * TPB;
                d4[i] = __ldcs(g4 + i);
            }
            {
                const int i = tid + 5 * TPB;
                if (i < 1472) d4[i] = __ldcs(g4 + i);
            }
            if (tid < 192) {
                float4 vq = __ldcs(gv + tid);
                float4 lq = __ldcs(gl + tid);
                __stcs(gl2 + 2 * tid + 0, make_float2(lq.x, lq.y));
                __stcs(gl2 + 2 * tid + 1, make_float2(lq.z, lq.w));
                vq.x = fmaf(0.1f, tanha(lq.x), vq.x);
                vq.y = fmaf(0.1f, tanha(lq.y), vq.y);
                vq.z = fmaf(0.1f, tanha(lq.z), vq.z);
                vq.w = fmaf(0.1f, tanha(lq.w), vq.w);
                dv[tid] = vq;
            }
        } else {
            const int nS = (nv * 23) >> 2;
            for (int i = tid; i < nS; i += TPB) d4[i] = __ldcs(g4 + i);
            const int n3 = (nv * 3) >> 2;
            for (int i = tid; i < n3; i += TPB) {
                float4 vq = __ldcs(gv + i);
                float4 lq = __ldcs(gl + i);
                __stcs(gl2 + 2 * i + 0, make_float2(lq.x, lq.y));
                __stcs(gl2 + 2 * i + 1, make_float2(lq.z, lq.w));
                vq.x = fmaf(0.1f, tanha(lq.x), vq.x);
                vq.y = fmaf(0.1f, tanha(lq.y), vq.y);
                vq.z = fmaf(0.1f, tanha(lq.z), vq.z);
                vq.w = fmaf(0.1f, tanha(lq.w), vq.w);
                dv[i] = vq;
            }
        }
    }

    cudaGridDependencySynchronize();
    __syncthreads();

    if (tid < nv) {
        float vx = s_vh[3 * tid + 0];
        float vy = s_vh[3 * tid + 1];
        float vz = s_vh[3 * tid + 2];

        u64 acc0 = 0, acc1 = 0, acc2 = 0, acc3 = 0, acc4 = 0, acc5 = 0;
        const u64* cA2 = (const u64*)c_pack;
        const float* skv = &s_sk[tid * 23];
        #pragma unroll
        for (int j = 0; j < J; j++) {
            const u64 w2 = pack2(skv[j]);
            fma2(acc0, w2, cA2[6 * j + 0]);
            fma2(acc1, w2, cA2[6 * j + 1]);
            fma2(acc2, w2, cA2[6 * j + 2]);
            fma2(acc3, w2, cA2[6 * j + 3]);
            fma2(acc4, w2, cA2[6 * j + 4]);
            fma2(acc5, w2, cA2[6 * j + 5]);
        }

        float t0x, t0y, t0z, t0w, t1x, t1y, t1z, t1w, t2x, t2y, t2z, t2w;
        unpack2(acc0, t0x, t0y); unpack2(acc1, t0z, t0w);
        unpack2(acc2, t1x, t1y); unpack2(acc3, t1z, t1w);
        unpack2(acc4, t2x, t2y); unpack2(acc5, t2z, t2w);

        float x = fmaf(t0x, vx, fmaf(t0y, vy, fmaf(t0z, vz, t0w)));
        float y = fmaf(t1x, vx, fmaf(t1y, vy, fmaf(t1z, vz, t1w)));
        float z = fmaf(t2x, vx, fmaf(t2y, vy, fmaf(t2z, vz, t2w)));

        float c = c_pack[276];
        // overwrite own slots only -> no barrier needed before writes
        s_vh[3 * tid + 0] = fmaf(c, x, c_pack[277]);
        s_vh[3 * tid + 1] = fmaf(c, y, c_pack[278]);
        s_vh[3 * tid + 2] = fmaf(c, z, c_pack[279]);
    }
    __syncthreads();

    // cooperative vectorized streaming stores (B broadcast copies)
    {
        const float4* r4 = (const float4*)s_vh;
        const long stride4 = V3 >> 2;
        if (full) {
            if (tid < 192) {
                const float4 val = r4[tid];
                float4* go = (float4*)(out + v0 * 3);
                for (int b = 0; b < B; b++) {
                    __stcs(go + tid, val);
                    go += stride4;
                }
            }
        } else {
            const int n3 = (nv * 3) >> 2;
            float4* go = (float4*)(out + v0 * 3);
            for (int b = 0; b < B; b++) {
                for (int i = tid; i < n3; i += TPB) __stcs(go + i, r4[i]);
                go += stride4;
            }
        }
    }
}

extern "C" void kernel_launch(void* const* d_in, const int* in_sizes, int n_in,
                              void* d_out, int out_size)
{
    const float* vt    = (const float*)d_in[0];
    const float* sk    = (const float*)d_in[1];
    const float* jr    = (const float*)d_in[2];
    const float* p0    = (const float*)d_in[3];
    const float* p1    = (const float*)d_in[4];
    const float* p2    = (const float*)d_in[5];
    const float* p3    = (const float*)d_in[6];
    const float* p4    = (const float*)d_in[7];
    const float* p5    = (const float*)d_in[8];
    const float* p12   = (const float*)d_in[9];
    const float* p13   = (const float*)d_in[10];
    const float* la    = (const float*)d_in[11];
    const float* disp  = (const float*)d_in[12];
    const float* scale = (const float*)d_in[13];
    const float* loc   = (const float*)d_in[14];
    float* out = (float*)d_out;

    int V = in_sizes[0] / 3;
    long fixed = 69L + 69L + 1L + 3L + 3L * (long)V;
    int B = (int)(((long)out_size - fixed) / (3L * (long)V));

    static float* cpack_dev = nullptr;
    if (!cpack_dev) {
        void* p = nullptr;
        cudaGetSymbolAddress(&p, c_pack);
        cpack_dev = (float*)p;
    }

    prep_kernel<<<1, 32>>>(cpack_dev, jr, p0, p1, p2, p3, p4, p5, p12, p13,
                           disp, scale, loc, out, B, V);

    int blocks = (V + VPB - 1) / VPB;

    cudaLaunchConfig_t cfg = {};
    cfg.gridDim  = dim3(blocks, 1, 1);
    cfg.blockDim = dim3(TPB, 1, 1);
    cfg.dynamicSmemBytes = 0;
    cfg.stream = 0;
    cudaLaunchAttribute attrs[1];
    attrs[0].id = cudaLaunchAttributeProgrammaticStreamSerialization;
    attrs[0].val.programmaticStreamSerializationAllowed = 1;
    cfg.attrs = attrs;
    cfg.numAttrs = 1;
    cudaLaunchKernelEx(&cfg, lbs_kernel, vt, sk, la, out, V, B);
}

// round 13
// speedup vs baseline: 1.0553x; 1.0073x over previous
#include <cuda_runtime.h>
#include <math.h>

#define J   23
#define TPB 256
#define VPB 256
#define PI_F 3.14159265358979323846f

__constant__ int cPAR[J] = {-1,0,1,1,3,4,5,4,7,4,9,1,11,12,13,12,15,12,17,0,19,0,21};

// packed A (69 float4 = 276 floats) + constants (c, ox, oy, oz) at [276..279]
__constant__ __align__(16) float c_pack[280];

typedef unsigned long long u64;

__device__ __forceinline__ void fma2(u64& d, u64 a, u64 b) {
    asm("fma.rn.f32x2 %0, %1, %2, %0;" : "+l"(d) : "l"(a), "l"(b));
}
__device__ __forceinline__ u64 pack2(float v) {
    u64 r;
    asm("mov.b64 %0, {%1, %1};" : "=l"(r) : "f"(v));
    return r;
}
__device__ __forceinline__ void unpack2(u64 v, float& lo, float& hi) {
    asm("mov.b64 {%0, %1}, %2;" : "=f"(lo), "=f"(hi) : "l"(v));
}
__device__ __forceinline__ float tanha(float x) {
    float y;
    asm("tanh.approx.f32 %0, %1;" : "=f"(y) : "f"(x));
    return y;
}

// ---------------- Prep: one warp; writes A + consts into the constant bank, triggers PDL ----------------
__global__ void __launch_bounds__(32) prep_kernel(
    float* __restrict__ cpack,
    const float* __restrict__ jr,
    const float* __restrict__ p0, const float* __restrict__ p1,
    const float* __restrict__ p2, const float* __restrict__ p3,
    const float* __restrict__ p4, const float* __restrict__ p5,
    const float* __restrict__ p12, const float* __restrict__ p13,
    const float* __restrict__ disp, const float* __restrict__ scale,
    const float* __restrict__ loc,
    float* __restrict__ out, int B, int V)
{
    __shared__ float s_Tl[J * 12];
    __shared__ float s_G[J * 12];
    __shared__ float s_pose[J * 3];

    const int tid = threadIdx.x;

    float cst = 0.f, ox = 0.f, oy = 0.f, oz = 0.f;
    if (tid == 31) {
        cst = 0.0035f * scale[0];
        ox = loc[0] + 0.1f * tanhf(disp[0]);
        oy = loc[1] + 0.1f * tanhf(disp[1]);
        oz = loc[2] + 0.1f * tanhf(disp[2]);
        cpack[276] = cst; cpack[277] = ox; cpack[278] = oy; cpack[279] = oz;
    }

    if (tid < J) {
        float fac = 0.f, sy = 1.f, sz = 1.f;
        const float* pp = p0;
        bool has = true;
        switch (tid) {
            case 0:  fac = PI_F / 2.f; pp = p0;  break;
            case 1:  fac = PI_F / 4.f; pp = p1;  break;
            case 2:  fac = PI_F / 9.f; pp = p2;  break;
            case 3:  fac = PI_F / 3.f; pp = p3;  break;
            case 4:  fac = PI_F / 3.f; pp = p4;  break;
            case 5:  fac = PI_F / 3.f; pp = p5;  break;
            case 11: fac = PI_F / 3.f; pp = p3;  sy = -1.f; sz = -1.f; break;
            case 12: fac = PI_F / 3.f; pp = p12; break;
            case 13: fac = PI_F / 3.f; pp = p13; break;
            default: has = false;
        }
        float px = 0.f, py = 0.f, pz = 0.f;
        if (has) {
            px = fac * tanhf(pp[0]);
            py = sy * fac * tanhf(pp[1]);
            pz = sz * fac * tanhf(pp[2]);
        }
        s_pose[3 * tid + 0] = px;
        s_pose[3 * tid + 1] = py;
        s_pose[3 * tid + 2] = pz;

        float ang = sqrtf(px * px + py * py + pz * pz + 1e-12f);
        float inv = 1.f / ang;
        float x = px * inv, y = py * inv, z = pz * inv;
        float s = __sinf(ang), c = __cosf(ang), t = 1.f - c;
        float* T = &s_Tl[tid * 12];
        T[0] = 1.f + t * (-(z * z) - (y * y));
        T[1] = -s * z + t * (x * y);
        T[2] =  s * y + t * (x * z);
        T[4] =  s * z + t * (x * y);
        T[5] = 1.f + t * (-(z * z) - (x * x));
        T[6] = -s * x + t * (y * z);
        T[8] = -s * y + t * (x * z);
        T[9] =  s * x + t * (y * z);
        T[10] = 1.f + t * (-(y * y) - (x * x));

        int par = cPAR[tid];
        float jx = jr[3 * tid], jy = jr[3 * tid + 1], jz = jr[3 * tid + 2];
        if (par >= 0) { jx -= jr[3 * par]; jy -= jr[3 * par + 1]; jz -= jr[3 * par + 2]; }
        T[3] = jx; T[7] = jy; T[11] = jz;
    }
    __syncwarp();

    if (tid < 12) s_G[tid] = s_Tl[tid];
    __syncwarp();
    #pragma unroll
    for (int j = 1; j < J; j++) {
        const int p = cPAR[j];
        if (tid < 12) {
            const int r = tid >> 2, c = tid & 3;
            const float* gp = &s_G[p * 12 + r * 4];
            const float* tl = &s_Tl[j * 12];
            float v = gp[0] * tl[0 * 4 + c]
                    + gp[1] * tl[1 * 4 + c]
                    + gp[2] * tl[2 * 4 + c];
            if (c == 3) v += gp[3];
            s_G[j * 12 + tid] = v;
        }
        __syncwarp();
    }

    if (tid < J) {
        const float* g = &s_G[tid * 12];
        float jx = jr[3 * tid], jy = jr[3 * tid + 1], jz = jr[3 * tid + 2];
        float tcx = g[0] * jx + g[1] * jy + g[2] * jz;
        float tcy = g[4] * jx + g[5] * jy + g[6] * jz;
        float tcz = g[8] * jx + g[9] * jy + g[10] * jz;
        float* a = &cpack[tid * 12];
        a[0] = g[0]; a[1] = g[1]; a[2]  = g[2];  a[3]  = g[3]  - tcx;
        a[4] = g[4]; a[5] = g[5]; a[6]  = g[6];  a[7]  = g[7]  - tcy;
        a[8] = g[8]; a[9] = g[9]; a[10] = g[10]; a[11] = g[11] - tcz;
    }
    __syncwarp();
    __threadfence();
    cudaTriggerProgrammaticLaunchCompletion();

    // small outputs (independent of lbs)
    const long V3 = 3L * (long)V;
    const long base = (long)B * V3;
    if (tid < J) {
        out[base + 3 * tid + 0] = s_pose[3 * tid + 0];
        out[base + 3 * tid + 1] = s_pose[3 * tid + 1];
        out[base + 3 * tid + 2] = s_pose[3 * tid + 2];
    }
    if (tid == 31) {
        for (int j = 0; j < J; j++) {
            out[base + 69 + 3 * j + 0] = fmaf(cst, s_G[j * 12 + 3],  ox);
            out[base + 69 + 3 * j + 1] = fmaf(cst, s_G[j * 12 + 7],  oy);
            out[base + 69 + 3 * j + 2] = fmaf(cst, s_G[j * 12 + 11], oz);
        }
        out[base + 138] = scale[0];
        out[base + 139] = disp[0];
        out[base + 140] = disp[1];
        out[base + 141] = disp[2];
    }
}

// ---------------- LBS: round-10 body + early PDL trigger after compute phase ----------------
__global__ void __launch_bounds__(TPB, 6) lbs_kernel(
    const float* __restrict__ vt,
    const float* __restrict__ sk,
    const float* __restrict__ la,
    float* __restrict__ out, int V, int B)
{
    __shared__ float s_sk[VPB * 23];
    __shared__ float s_vt[VPB * 3];    // reused for results after compute
    __shared__ float s_la[VPB * 3];

    const int tid = threadIdx.x;
    const long v0 = (long)blockIdx.x * VPB;
    const int nv  = (V - (int)v0 < VPB) ? (V - (int)v0) : VPB;
    const long V3 = 3L * (long)V;
    const bool full = (nv == VPB);
    const long offLa = (long)B * V3 + 142;

    // ---- PDL preamble: tile loads + la passthrough (no dependency on prep) ----
    {
        const float4* g4 = (const float4*)(sk + v0 * 23);
        float4* d4 = (float4*)s_sk;
        const float4* gv = (const float4*)(vt + v0 * 3);
        const float4* gl = (const float4*)(la + v0 * 3);
        float4* dv = (float4*)s_vt;
        float4* dl = (float4*)s_la;
        float2* gl2 = (float2*)(out + offLa + v0 * 3);
        if (full) {
            #pragma unroll
            for (int k = 0; k < 5; k++) {
                const int i = tid + k * TPB;
                d4[i] = __ldcs(g4 + i);
            }
            {
                const int i = tid + 5 * TPB;
                if (i < 1472) d4[i] = __ldcs(g4 + i);
            }
            if (tid < 192) {
                dv[tid] = __ldcs(gv + tid);
                float4 lq = __ldcs(gl + tid);
                dl[tid] = lq;
                __stcs(gl2 + 2 * tid + 0, make_float2(lq.x, lq.y));
                __stcs(gl2 + 2 * tid + 1, make_float2(lq.z, lq.w));
            }
        } else {
            const int nS = (nv * 23) >> 2;
            for (int i = tid; i < nS; i += TPB) d4[i] = __ldcs(g4 + i);
            const int n3 = (nv * 3) >> 2;
            for (int i = tid; i < n3; i += TPB) {
                dv[i] = __ldcs(gv + i);
                float4 lq = __ldcs(gl + i);
                dl[i] = lq;
                __stcs(gl2 + 2 * i + 0, make_float2(lq.x, lq.y));
                __stcs(gl2 + 2 * i + 1, make_float2(lq.z, lq.w));
            }
        }
    }

    cudaGridDependencySynchronize();
    __syncthreads();

    if (tid < nv) {
        float la0 = s_la[3 * tid + 0], la1 = s_la[3 * tid + 1], la2 = s_la[3 * tid + 2];
        float vx = s_vt[3 * tid + 0] + 0.1f * tanha(la0);
        float vy = s_vt[3 * tid + 1] + 0.1f * tanha(la1);
        float vz = s_vt[3 * tid + 2] + 0.1f * tanha(la2);

        u64 acc0 = 0, acc1 = 0, acc2 = 0, acc3 = 0, acc4 = 0, acc5 = 0;
        const u64* cA2 = (const u64*)c_pack;
        const float* skv = &s_sk[tid * 23];
        #pragma unroll
        for (int j = 0; j < J; j++) {
            const u64 w2 = pack2(skv[j]);
            fma2(acc0, w2, cA2[6 * j + 0]);
            fma2(acc1, w2, cA2[6 * j + 1]);
            fma2(acc2, w2, cA2[6 * j + 2]);
            fma2(acc3, w2, cA2[6 * j + 3]);
            fma2(acc4, w2, cA2[6 * j + 4]);
            fma2(acc5, w2, cA2[6 * j + 5]);
        }

        float t0x, t0y, t0z, t0w, t1x, t1y, t1z, t1w, t2x, t2y, t2z, t2w;
        unpack2(acc0, t0x, t0y); unpack2(acc1, t0z, t0w);
        unpack2(acc2, t1x, t1y); unpack2(acc3, t1z, t1w);
        unpack2(acc4, t2x, t2y); unpack2(acc5, t2z, t2w);

        float x = fmaf(t0x, vx, fmaf(t0y, vy, fmaf(t0z, vz, t0w)));
        float y = fmaf(t1x, vx, fmaf(t1y, vy, fmaf(t1z, vz, t1w)));
        float z = fmaf(t2x, vx, fmaf(t2y, vy, fmaf(t2z, vz, t2w)));

        float c = c_pack[276];
        // overwrite own slots only -> no barrier needed before writes
        s_vt[3 * tid + 0] = fmaf(c, x, c_pack[277]);
        s_vt[3 * tid + 1] = fmaf(c, y, c_pack[278]);
        s_vt[3 * tid + 2] = fmaf(c, z, c_pack[279]);
    }
    __syncthreads();

    // All c_pack reads complete for this block -> allow next replay's prep to dispatch.
    // (Trigger fires once ALL blocks pass this point; prep rewrites identical values.)
    cudaTriggerProgrammaticLaunchCompletion();

    // cooperative vectorized streaming stores (B broadcast copies)
    {
        const float4* r4 = (const float4*)s_vt;
        const long stride4 = V3 >> 2;
        if (full) {
            if (tid < 192) {
                const float4 val = r4[tid];
                float4* go = (float4*)(out + v0 * 3);
                for (int b = 0; b < B; b++) {
                    __stcs(go + tid, val);
                    go += stride4;
                }
            }
        } else {
            const int n3 = (nv * 3) >> 2;
            float4* go = (float4*)(out + v0 * 3);
            for (int b = 0; b < B; b++) {
                for (int i = tid; i < n3; i += TPB) __stcs(go + i, r4[i]);
                go += stride4;
            }
        }
    }
}

extern "C" void kernel_launch(void* const* d_in, const int* in_sizes, int n_in,
                              void* d_out, int out_size)
{
    const float* vt    = (const float*)d_in[0];
    const float* sk    = (const float*)d_in[1];
    const float* jr    = (const float*)d_in[2];
    const float* p0    = (const float*)d_in[3];
    const float* p1    = (const float*)d_in[4];
    const float* p2    = (const float*)d_in[5];
    const float* p3    = (const float*)d_in[6];
    const float* p4    = (const float*)d_in[7];
    const float* p5    = (const float*)d_in[8];
    const float* p12   = (const float*)d_in[9];
    const float* p13   = (const float*)d_in[10];
    const float* la    = (const float*)d_in[11];
    const float* disp  = (const float*)d_in[12];
    const float* scale = (const float*)d_in[13];
    const float* loc   = (const float*)d_in[14];
    float* out = (float*)d_out;

    int V = in_sizes[0] / 3;
    long fixed = 69L + 69L + 1L + 3L + 3L * (long)V;
    int B = (int)(((long)out_size - fixed) / (3L * (long)V));

    static float* cpack_dev = nullptr;
    if (!cpack_dev) {
        void* p = nullptr;
        cudaGetSymbolAddress(&p, c_pack);
        cpack_dev = (float*)p;
    }

    cudaLaunchAttribute attrs[1];
    attrs[0].id = cudaLaunchAttributeProgrammaticStreamSerialization;
    attrs[0].val.programmaticStreamSerializationAllowed = 1;

    // prep: PDL-relaxed against the PREVIOUS kernel in stream (prior replay's lbs).
    // prep is idempotent, so overlapping it with the prior lbs tail is safe.
    {
        cudaLaunchConfig_t pcfg = {};
        pcfg.gridDim  = dim3(1, 1, 1);
        pcfg.blockDim = dim3(32, 1, 1);
        pcfg.dynamicSmemBytes = 0;
        pcfg.stream = 0;
        pcfg.attrs = attrs;
        pcfg.numAttrs = 1;
        cudaLaunchKernelEx(&pcfg, prep_kernel,
                           cpack_dev, jr, p0, p1, p2, p3, p4, p5, p12, p13,
                           disp, scale, loc, out, B, V);
    }

    int blocks = (V + VPB - 1) / VPB;
    {
        cudaLaunchConfig_t cfg = {};
        cfg.gridDim  = dim3(blocks, 1, 1);
        cfg.blockDim = dim3(TPB, 1, 1);
        cfg.dynamicSmemBytes = 0;
        cfg.stream = 0;
        cfg.attrs = attrs;
        cfg.numAttrs = 1;
        cudaLaunchKernelEx(&cfg, lbs_kernel, vt, sk, la, out, V, B);
    }
}